// round 13
// baseline (speedup 1.0000x reference)
#include <cuda_runtime.h>
#include <cuda_bf16.h>
#include <math.h>

#define NL 4
#define D 512
#define H 8
#define DFF 2048
#define T 256
#define B 8
#define NBUCK 33
#define DH 64
#define MTOK (B*T)   // 2048
#define NQKV 1536

// bf16 weight buffer offsets (elements)
#define QKVW_OFF 0
#define WO_OFF   (NL*NQKV*D)
#define W1_OFF   (WO_OFF + NL*D*D)
#define W2_OFF   (W1_OFF + NL*DFF*D)
#define WTOT     (W2_OFF + NL*D*DFF)

// prep granule counts (float4 granules)
#define QKV4 (NL*NQKV*D/4)
#define WO4  (NL*D*D/4)
#define WFF4 (NL*DFF*D/4)
#define PREP_TOT (QKV4 + WO4 + 2*WFF4)

// ---------------- scratch ----------------
__device__ float g_x[MTOK*D];
__device__ float g_out[MTOK*D];
__device__ float g_qkv[MTOK*NQKV];
__device__ float g_bqkv[NL*NQKV];
__device__ __nv_bfloat16 g_hb[MTOK*D];
__device__ __nv_bfloat16 g_ctxb[MTOK*D];
__device__ __nv_bfloat16 g_hidb[MTOK*DFF];
__device__ __nv_bfloat16 g_wbf[WTOT];

// ---------------- merged weight prep (weights + qkv bias) -------------------
__global__ void prep_w(const float* __restrict__ Wq, const float* __restrict__ Wk,
                       const float* __restrict__ Wv, const float* __restrict__ Wo,
                       const float* __restrict__ W1, const float* __restrict__ W2,
                       const float* __restrict__ bq, const float* __restrict__ bk,
                       const float* __restrict__ bv) {
    int i = blockIdx.x * blockDim.x + threadIdx.x;
    if (i < QKV4) {
        int e = i * 4;
        int l = e / (NQKV*D);
        int rem = e - l * (NQKV*D);
        int r = rem / D;
        int c = rem - r * D;
        const float* s = (r < 512) ? Wq : (r < 1024) ? Wk : Wv;
        float4 v = *(const float4*)(s + (size_t)l*D*D + (size_t)(r & 511)*D + c);
        __nv_bfloat162* o = (__nv_bfloat162*)(g_wbf + QKVW_OFF + e);
        o[0] = __floats2bfloat162_rn(v.x, v.y);
        o[1] = __floats2bfloat162_rn(v.z, v.w);
    } else if (i < QKV4 + WO4) {
        int j = i - QKV4;
        float4 v = ((const float4*)Wo)[j];
        __nv_bfloat162* o = (__nv_bfloat162*)(g_wbf + WO_OFF + (size_t)j*4);
        o[0] = __floats2bfloat162_rn(v.x, v.y);
        o[1] = __floats2bfloat162_rn(v.z, v.w);
    } else if (i < QKV4 + WO4 + WFF4) {
        int j = i - QKV4 - WO4;
        float4 v = ((const float4*)W1)[j];
        __nv_bfloat162* o = (__nv_bfloat162*)(g_wbf + W1_OFF + (size_t)j*4);
        o[0] = __floats2bfloat162_rn(v.x, v.y);
        o[1] = __floats2bfloat162_rn(v.z, v.w);
    } else if (i < PREP_TOT) {
        int j = i - QKV4 - WO4 - WFF4;
        float4 v = ((const float4*)W2)[j];
        __nv_bfloat162* o = (__nv_bfloat162*)(g_wbf + W2_OFF + (size_t)j*4);
        o[0] = __floats2bfloat162_rn(v.x, v.y);
        o[1] = __floats2bfloat162_rn(v.z, v.w);
    } else if (i < PREP_TOT + NL*NQKV) {
        int j = i - PREP_TOT;
        int l = j / NQKV, n = j - l*NQKV;
        float v = (n < 512) ? bq[l*D + n] : (n < 1024) ? bk[l*D + n - 512] : bv[l*D + n - 1024];
        g_bqkv[j] = v;
    }
}

// ---------------- embedding ------------------------------------------------
__global__ void embed_kernel(const float* __restrict__ src) {
    int i = blockIdx.x * blockDim.x + threadIdx.x;
    if (i >= MTOK * D) return;
    int d = i & (D - 1);
    int t = (i / D) & (T - 1);
    int b = i / (D * T);
    float ang = (float)t * expf(-(float)(d & ~1) * (logf(10000.0f) / (float)D));
    float pe = (d & 1) ? cosf(ang) : sinf(ang);
    g_x[i] = src[((t * B) + b) * D + d] * sqrtf((float)D) + pe;
}

// ---------------- warp-per-token layernorm -> bf16 -------------------------
__global__ __launch_bounds__(256) void ln_kernel(const float* __restrict__ in,
                                                 __nv_bfloat16* __restrict__ out,
                                                 const float* __restrict__ gam,
                                                 const float* __restrict__ bet) {
    int lane = threadIdx.x & 31, w = threadIdx.x >> 5;
    int tok = blockIdx.x * 8 + w;
    const float4* row = (const float4*)(in + (size_t)tok * D);
    float4 v[4];
    float s = 0.f;
    #pragma unroll
    for (int j = 0; j < 4; j++) {
        v[j] = row[lane + 32*j];
        s += v[j].x + v[j].y + v[j].z + v[j].w;
    }
    #pragma unroll
    for (int o = 16; o; o >>= 1) s += __shfl_xor_sync(0xffffffffu, s, o);
    float mean = s * (1.0f / D);
    float sq = 0.f;
    #pragma unroll
    for (int j = 0; j < 4; j++) {
        v[j].x -= mean; v[j].y -= mean; v[j].z -= mean; v[j].w -= mean;
        sq += v[j].x*v[j].x + v[j].y*v[j].y + v[j].z*v[j].z + v[j].w*v[j].w;
    }
    #pragma unroll
    for (int o = 16; o; o >>= 1) sq += __shfl_xor_sync(0xffffffffu, sq, o);
    float inv = rsqrtf(sq * (1.0f / D) + 1e-6f);
    __nv_bfloat162* o2 = (__nv_bfloat162*)(out + (size_t)tok * D);
    #pragma unroll
    for (int j = 0; j < 4; j++) {
        int idx = lane + 32*j;
        float4 gv = ((const float4*)gam)[idx];
        float4 bv = ((const float4*)bet)[idx];
        o2[2*idx]   = __floats2bfloat162_rn(v[j].x * inv * gv.x + bv.x, v[j].y * inv * gv.y + bv.y);
        o2[2*idx+1] = __floats2bfloat162_rn(v[j].z * inv * gv.z + bv.z, v[j].w * inv * gv.w + bv.w);
    }
}

// ---------------- mma helpers ----------------------------------------------
__device__ __forceinline__ void mma_bf16(float* d, const unsigned* a, unsigned b0, unsigned b1) {
    asm volatile("mma.sync.aligned.m16n8k16.row.col.f32.bf16.bf16.f32 "
        "{%0,%1,%2,%3},{%4,%5,%6,%7},{%8,%9},{%0,%1,%2,%3};\n"
        : "+f"(d[0]), "+f"(d[1]), "+f"(d[2]), "+f"(d[3])
        : "r"(a[0]), "r"(a[1]), "r"(a[2]), "r"(a[3]), "r"(b0), "r"(b1));
}
__device__ __forceinline__ void ldsm4(unsigned* r, unsigned addr) {
    asm volatile("ldmatrix.sync.aligned.m8n8.x4.shared.b16 {%0,%1,%2,%3},[%4];\n"
        : "=r"(r[0]), "=r"(r[1]), "=r"(r[2]), "=r"(r[3]) : "r"(addr));
}
__device__ __forceinline__ void cp16(unsigned dst, const void* src) {
    asm volatile("cp.async.cg.shared.global [%0], [%1], 16;\n" :: "r"(dst), "l"(src));
}
__device__ __forceinline__ void cp_commit() { asm volatile("cp.async.commit_group;\n"); }
__device__ __forceinline__ void cp_wait0() { asm volatile("cp.async.wait_group 0;\n"); }
__device__ __forceinline__ void cp_wait1() { asm volatile("cp.async.wait_group 1;\n"); }
__device__ __forceinline__ unsigned packbf(float x, float y) {
    __nv_bfloat162 t = __floats2bfloat162_rn(x, y);
    return *(unsigned*)&t;
}

// ---------------- tensor-core GEMM, 3-stage cp.async -----------------------
// 128 threads, 4 warps in 2(m) x 2(n); warp tile (BM/2) x 32; BN = 64.
// 3 stages keep 2 tile-loads in flight (wait_group 1).
#define GP 72
#define GSMEM(BM) (3 * ((BM) + 64) * GP * 2)

template<int BM>
__global__ __launch_bounds__(128, (BM == 128) ? 2 : 4) void gemm_tc(
    const __nv_bfloat16* __restrict__ A, const __nv_bfloat16* __restrict__ W,
    const float* __restrict__ bias, const float* __restrict__ resid,
    float* __restrict__ Cf, __nv_bfloat16* __restrict__ Cb,
    int M, int N, int K, float scale, int n_lo, int relu)
{
    constexpr int MT = BM / 32;
    constexpr int AROWS = BM / 16;
    extern __shared__ __nv_bfloat16 smg[];
    __nv_bfloat16* As = smg;                  // [3][BM*GP]
    __nv_bfloat16* Bs = smg + 3*BM*GP;        // [3][64*GP]
    int tid = threadIdx.x;
    int lane = tid & 31, wid = tid >> 5;
    int wm = wid & 1, wn = wid >> 1;
    int m0 = blockIdx.y * BM, n0 = blockIdx.x << 6;

    int a_row = wm * (BM/2) + (lane & 15);
    int a_koff = (lane >> 4) << 3;
    int b_row = (wn << 5) + (lane & 7) + ((lane >> 4) << 3);
    int b_koff = ((lane >> 3) & 1) << 3;
    unsigned As_base = (unsigned)__cvta_generic_to_shared(As);
    unsigned Bs_base = (unsigned)__cvta_generic_to_shared(Bs);

    float acc[MT][4][4];
    #pragma unroll
    for (int i = 0; i < MT; i++)
        #pragma unroll
        for (int j = 0; j < 4; j++)
            #pragma unroll
            for (int r = 0; r < 4; r++) acc[i][j][r] = 0.f;

    const int KT = K >> 6;
    int c_row = tid >> 3, c_kc = (tid & 7) << 3;

    const __nv_bfloat16* Ag = A + (size_t)m0 * K;
    const __nv_bfloat16* Wg = W + (size_t)n0 * K;

    auto issue = [&](int kt, int s) {
        const __nv_bfloat16* a = Ag + (kt << 6);
        const __nv_bfloat16* w = Wg + (kt << 6);
        unsigned sa = As_base + (unsigned)((s * BM * GP) << 1);
        unsigned sb = Bs_base + (unsigned)((s * 64 * GP) << 1);
        #pragma unroll
        for (int i = 0; i < AROWS; i++) {
            int r = c_row + (i << 4);
            cp16(sa + (unsigned)((r * GP + c_kc) << 1), a + (size_t)r * K + c_kc);
        }
        #pragma unroll
        for (int i = 0; i < 4; i++) {
            int r = c_row + (i << 4);
            cp16(sb + (unsigned)((r * GP + c_kc) << 1), w + (size_t)r * K + c_kc);
        }
        cp_commit();
    };

    issue(0, 0);
    if (KT > 1) issue(1, 1);
    for (int kt = 0; kt < KT; kt++) {
        if (kt + 1 < KT) cp_wait1(); else cp_wait0();
        __syncthreads();
        if (kt + 2 < KT) issue(kt + 2, (kt + 2) % 3);
        int s = kt % 3;
        unsigned sa = As_base + (unsigned)((s * BM * GP) << 1);
        unsigned sb = Bs_base + (unsigned)((s * 64 * GP) << 1);
        #pragma unroll
        for (int st = 0; st < 4; st++) {
            unsigned av[MT][4], bv[2][4];
            unsigned abase = sa + (unsigned)((a_row * GP + (st << 4) + a_koff) << 1);
            #pragma unroll
            for (int i = 0; i < MT; i++)
                ldsm4(av[i], abase + (unsigned)((i << 4) * GP * 2));
            unsigned bbase = sb + (unsigned)((b_row * GP + (st << 4) + b_koff) << 1);
            ldsm4(bv[0], bbase);
            ldsm4(bv[1], bbase + (16 * GP * 2));
            #pragma unroll
            for (int i = 0; i < MT; i++)
                #pragma unroll
                for (int j = 0; j < 2; j++) {
                    mma_bf16(acc[i][2*j],   av[i], bv[j][0], bv[j][1]);
                    mma_bf16(acc[i][2*j+1], av[i], bv[j][2], bv[j][3]);
                }
        }
        __syncthreads();
    }

    float sc = (n0 < n_lo) ? scale : 1.0f;
    int rbase = m0 + wm * (BM/2) + (lane >> 2);
    int cbase = n0 + (wn << 5) + ((lane & 3) << 1);
    #pragma unroll
    for (int i = 0; i < MT; i++) {
        #pragma unroll
        for (int j = 0; j < 4; j++) {
            int r0 = rbase + (i << 4);
            int cc = cbase + (j << 3);
            float2 bb = *(const float2*)&bias[cc];
            float o0 = (acc[i][j][0] + bb.x) * sc;
            float o1 = (acc[i][j][1] + bb.y) * sc;
            float o2 = (acc[i][j][2] + bb.x) * sc;
            float o3 = (acc[i][j][3] + bb.y) * sc;
            if (relu) {
                o0 = fmaxf(o0, 0.f); o1 = fmaxf(o1, 0.f);
                o2 = fmaxf(o2, 0.f); o3 = fmaxf(o3, 0.f);
            }
            if (resid) {
                float2 ra = *(const float2*)&resid[(size_t)r0 * N + cc];
                float2 rb = *(const float2*)&resid[(size_t)(r0 + 8) * N + cc];
                o0 += ra.x; o1 += ra.y; o2 += rb.x; o3 += rb.y;
            }
            if (Cf) {
                *(float2*)&Cf[(size_t)r0 * N + cc] = make_float2(o0, o1);
                *(float2*)&Cf[(size_t)(r0 + 8) * N + cc] = make_float2(o2, o3);
            }
            if (Cb) {
                *(__nv_bfloat162*)&Cb[(size_t)r0 * N + cc] = __floats2bfloat162_rn(o0, o1);
                *(__nv_bfloat162*)&Cb[(size_t)(r0 + 8) * N + cc] = __floats2bfloat162_rn(o2, o3);
            }
        }
    }
}

// ---------------- tensor-core flash attention (+ fused srel) ---------------
// V staged coalesced into Vst[key][dh], then smem-transposed into Vtsm.
#define KS 72
#define VS 264
#define QS 72
#define VSTS 72
#define ATTN_SMEM_BYTES ((256*KS + 64*VS + 128*QS)*2 + (33*65 + 128*36)*4 + 256*VSTS*2)

__global__ __launch_bounds__(256) void attn_tc_kernel(const int* __restrict__ distances,
                                                      const int* __restrict__ lengths,
                                                      const float* __restrict__ uvec,
                                                      const float* __restrict__ vvec,
                                                      const float* __restrict__ rel_table) {
    extern __shared__ char smraw[];
    __nv_bfloat16* Ksm  = (__nv_bfloat16*)smraw;
    __nv_bfloat16* Vtsm = Ksm + 256*KS;
    __nv_bfloat16* Qsm  = Vtsm + 64*VS;
    float* relsm  = (float*)(Qsm + 128*QS);
    float* srelsm = relsm + 33*65;
    __nv_bfloat16* Vst = (__nv_bfloat16*)(srelsm + 128*36);   // [256][VSTS]

    int bh = blockIdx.x;
    int b = bh >> 3, h = bh & 7;
    int q0 = blockIdx.y << 7;
    int tid = threadIdx.x, lane = tid & 31, wid = tid >> 5;
    int len = lengths[b];
    int bT = b * T;
    const float* base = g_qkv + (size_t)bT * NQKV;

    for (int i = tid; i < 256*32; i += 256) {
        int key = i >> 5, dp = (i & 31) << 1;
        float2 kv = *(const float2*)(base + (size_t)key*NQKV + 512 + h*64 + dp);
        *(__nv_bfloat162*)&Ksm[key*KS + dp] = __floats2bfloat162_rn(kv.x, kv.y);
    }
    for (int i = tid; i < 256*32; i += 256) {
        int key = i >> 5, dp = (i & 31) << 1;
        float2 vv = *(const float2*)(base + (size_t)key*NQKV + 1024 + h*64 + dp);
        *(__nv_bfloat162*)&Vst[key*VSTS + dp] = __floats2bfloat162_rn(vv.x, vv.y);
    }
    for (int i = tid; i < 33*64; i += 256) {
        int bk = i >> 6, d2 = i & 63;
        relsm[bk*65 + d2] = rel_table[bk*D + h*64 + d2];
    }
    for (int i = tid; i < 128*32; i += 256) {
        int q = i >> 5, dp = (i & 31) << 1;
        float2 qv = *(const float2*)(base + (size_t)(q0+q)*NQKV + h*64 + dp);
        float2 uu = *(const float2*)(uvec + h*64 + dp);
        *(__nv_bfloat162*)&Qsm[q*QS + dp] = __floats2bfloat162_rn(qv.x+uu.x, qv.y+uu.y);
    }
    __syncthreads();

    for (int i = tid; i < 64*128; i += 256) {
        int dh = i >> 7, kp = (i & 127) << 1;
        __nv_bfloat162 t;
        t.x = Vst[kp*VSTS + dh];
        t.y = Vst[(kp+1)*VSTS + dh];
        *(__nv_bfloat162*)&Vtsm[dh*VS + kp] = t;
    }

    int wq = wid << 4;
    for (int qi = 0; qi < 16; qi++) {
        int q = q0 + wq + qi;
        float qv0 = base[(size_t)q*NQKV + h*64 + lane]      + vvec[h*64 + lane];
        float qv1 = base[(size_t)q*NQKV + h*64 + 32 + lane] + vvec[h*64 + 32 + lane];
        const float* rrow = relsm + lane*65;
        float acc = 0.f;
        #pragma unroll
        for (int d2 = 0; d2 < 32; d2++)
            acc += __shfl_sync(0xffffffffu, qv0, d2) * rrow[d2];
        #pragma unroll
        for (int d2 = 0; d2 < 32; d2++)
            acc += __shfl_sync(0xffffffffu, qv1, d2) * rrow[32 + d2];
        srelsm[(wq+qi)*36 + lane] = acc;
        if (lane == 0) srelsm[(wq+qi)*36 + 32] = 0.f;
    }
    __syncthreads();

    unsigned Ks_base = (unsigned)__cvta_generic_to_shared(Ksm);
    unsigned Vs_base = (unsigned)__cvta_generic_to_shared(Vtsm);
    unsigned Qs_base = (unsigned)__cvta_generic_to_shared(Qsm);

    int a_row_q = wq + (lane & 15);
    int a_koff = (lane >> 4) << 3;
    int b_nrow = (lane & 7) + ((lane >> 4) << 3);
    int b_koff = ((lane >> 3) & 1) << 3;
    int r_lo = lane >> 2;
    int c4 = (lane & 3) << 1;

    float m_i0 = -1e30f, m_i1 = -1e30f, l_i0 = 0.f, l_i1 = 0.f;
    float ctx[8][4];
    #pragma unroll
    for (int t = 0; t < 8; t++)
        #pragma unroll
        for (int r = 0; r < 4; r++) ctx[t][r] = 0.f;

    for (int kc = 0; kc < 2; kc++) {
        int kbase = kc << 7;
        float S[16][4];
        #pragma unroll
        for (int j = 0; j < 16; j++)
            #pragma unroll
            for (int r = 0; r < 4; r++) S[j][r] = 0.f;

        #pragma unroll
        for (int st = 0; st < 4; st++) {
            unsigned av[4];
            ldsm4(av, Qs_base + (unsigned)((a_row_q*QS + (st << 4) + a_koff) << 1));
            #pragma unroll
            for (int j2 = 0; j2 < 8; j2++) {
                unsigned bv[4];
                ldsm4(bv, Ks_base + (unsigned)(((kbase + (j2 << 4) + b_nrow)*KS + (st << 4) + b_koff) << 1));
                mma_bf16(S[2*j2],   av, bv[0], bv[1]);
                mma_bf16(S[2*j2+1], av, bv[2], bv[3]);
            }
        }

        int qrow = wq + r_lo;
        const int* drow0 = distances + (size_t)(bT + q0 + qrow) * T + kbase + c4;
        const int* drow1 = drow0 + 8 * T;
        const float* sr0 = srelsm + qrow * 36;
        const float* sr1 = sr0 + 8 * 36;
        float mn0 = m_i0, mn1 = m_i1;
        #pragma unroll
        for (int j = 0; j < 16; j++) {
            int k = kbase + (j << 3) + c4;
            float s0 = S[j][0] + sr0[drow0[j*8]];
            float s1 = S[j][1] + sr0[drow0[j*8 + 1]];
            float s2 = S[j][2] + sr1[drow1[j*8]];
            float s3 = S[j][3] + sr1[drow1[j*8 + 1]];
            bool v0 = k < len, v1 = (k + 1) < len;
            s0 = v0 ? s0 : -1e30f; s1 = v1 ? s1 : -1e30f;
            s2 = v0 ? s2 : -1e30f; s3 = v1 ? s3 : -1e30f;
            S[j][0] = s0; S[j][1] = s1; S[j][2] = s2; S[j][3] = s3;
            mn0 = fmaxf(mn0, fmaxf(s0, s1));
            mn1 = fmaxf(mn1, fmaxf(s2, s3));
        }
        mn0 = fmaxf(mn0, __shfl_xor_sync(0xffffffffu, mn0, 1));
        mn0 = fmaxf(mn0, __shfl_xor_sync(0xffffffffu, mn0, 2));
        mn1 = fmaxf(mn1, __shfl_xor_sync(0xffffffffu, mn1, 1));
        mn1 = fmaxf(mn1, __shfl_xor_sync(0xffffffffu, mn1, 2));

        float ps0 = __expf(m_i0 - mn0), ps1 = __expf(m_i1 - mn1);
        float ls0 = 0.f, ls1 = 0.f;
        #pragma unroll
        for (int j = 0; j < 16; j++) {
            S[j][0] = __expf(S[j][0] - mn0);
            S[j][1] = __expf(S[j][1] - mn0);
            S[j][2] = __expf(S[j][2] - mn1);
            S[j][3] = __expf(S[j][3] - mn1);
            ls0 += S[j][0] + S[j][1];
            ls1 += S[j][2] + S[j][3];
        }
        ls0 += __shfl_xor_sync(0xffffffffu, ls0, 1);
        ls0 += __shfl_xor_sync(0xffffffffu, ls0, 2);
        ls1 += __shfl_xor_sync(0xffffffffu, ls1, 1);
        ls1 += __shfl_xor_sync(0xffffffffu, ls1, 2);
        l_i0 = l_i0 * ps0 + ls0;
        l_i1 = l_i1 * ps1 + ls1;
        m_i0 = mn0; m_i1 = mn1;
        #pragma unroll
        for (int t = 0; t < 8; t++) {
            ctx[t][0] *= ps0; ctx[t][1] *= ps0;
            ctx[t][2] *= ps1; ctx[t][3] *= ps1;
        }

        #pragma unroll
        for (int t = 0; t < 8; t++) {
            unsigned aP[4];
            aP[0] = packbf(S[2*t][0],   S[2*t][1]);
            aP[1] = packbf(S[2*t][2],   S[2*t][3]);
            aP[2] = packbf(S[2*t+1][0], S[2*t+1][1]);
            aP[3] = packbf(S[2*t+1][2], S[2*t+1][3]);
            #pragma unroll
            for (int v4 = 0; v4 < 4; v4++) {
                unsigned bv[4];
                ldsm4(bv, Vs_base + (unsigned)((((v4 << 4) + b_nrow)*VS + kbase + (t << 4) + b_koff) << 1));
                mma_bf16(ctx[2*v4],   aP, bv[0], bv[1]);
                mma_bf16(ctx[2*v4+1], aP, bv[2], bv[3]);
            }
        }
    }

    float inv0 = 1.0f / l_i0, inv1 = 1.0f / l_i1;
    int qa = bT + q0 + wq + r_lo;
    #pragma unroll
    for (int t = 0; t < 8; t++) {
        int dh = ((t >> 1) << 4) + ((t & 1) << 3) + c4;
        *(__nv_bfloat162*)&g_ctxb[(size_t)qa * D + h*64 + dh] =
            __floats2bfloat162_rn(ctx[t][0] * inv0, ctx[t][1] * inv0);
        *(__nv_bfloat162*)&g_ctxb[(size_t)(qa + 8) * D + h*64 + dh] =
            __floats2bfloat162_rn(ctx[t][2] * inv1, ctx[t][3] * inv1);
    }
}

// ---------------- final LN + transpose (warp per token) --------------------
__global__ __launch_bounds__(256) void final_kernel(const float* __restrict__ gam,
                                                    const float* __restrict__ bet,
                                                    float* __restrict__ out) {
    int lane = threadIdx.x & 31, w = threadIdx.x >> 5;
    int tok = blockIdx.x * 8 + w;
    int b = tok / T, t = tok % T;
    const float4* row = (const float4*)(g_x + (size_t)tok * D);
    float4 v[4];
    float s = 0.f;
    #pragma unroll
    for (int j = 0; j < 4; j++) {
        v[j] = row[lane + 32*j];
        s += v[j].x + v[j].y + v[j].z + v[j].w;
    }
    #pragma unroll
    for (int o = 16; o; o >>= 1) s += __shfl_xor_sync(0xffffffffu, s, o);
    float mean = s * (1.0f / D);
    float sq = 0.f;
    #pragma unroll
    for (int j = 0; j < 4; j++) {
        v[j].x -= mean; v[j].y -= mean; v[j].z -= mean; v[j].w -= mean;
        sq += v[j].x*v[j].x + v[j].y*v[j].y + v[j].z*v[j].z + v[j].w*v[j].w;
    }
    #pragma unroll
    for (int o = 16; o; o >>= 1) sq += __shfl_xor_sync(0xffffffffu, sq, o);
    float inv = rsqrtf(sq * (1.0f / D) + 1e-6f);
    float4* orow = (float4*)(out + (size_t)((t * B) + b) * D);
    #pragma unroll
    for (int j = 0; j < 4; j++) {
        int idx = lane + 32*j;
        float4 gv = ((const float4*)gam)[idx];
        float4 bv = ((const float4*)bet)[idx];
        float4 o;
        o.x = v[j].x * inv * gv.x + bv.x;
        o.y = v[j].y * inv * gv.y + bv.y;
        o.z = v[j].z * inv * gv.z + bv.z;
        o.w = v[j].w * inv * gv.w + bv.w;
        orow[idx] = o;
    }
}

// ---------------- host ----------------
extern "C" void kernel_launch(void* const* d_in, const int* in_sizes, int n_in,
                              void* d_out, int out_size) {
    const float* src       = (const float*)d_in[0];
    const int*   lengths   = (const int*)  d_in[1];
    const int*   distances = (const int*)  d_in[2];
    const float* u         = (const float*)d_in[3];
    const float* v         = (const float*)d_in[4];
    const float* ln1_g     = (const float*)d_in[5];
    const float* ln1_b     = (const float*)d_in[6];
    const float* Wq        = (const float*)d_in[7];
    const float* Wk        = (const float*)d_in[8];
    const float* Wv        = (const float*)d_in[9];
    const float* Wo        = (const float*)d_in[10];
    const float* bq        = (const float*)d_in[11];
    const float* bk        = (const float*)d_in[12];
    const float* bv        = (const float*)d_in[13];
    const float* bo        = (const float*)d_in[14];
    const float* rel_table = (const float*)d_in[15];
    const float* ffn_ln_g  = (const float*)d_in[16];
    const float* ffn_ln_b  = (const float*)d_in[17];
    const float* W1        = (const float*)d_in[18];
    const float* b1        = (const float*)d_in[19];
    const float* W2        = (const float*)d_in[20];
    const float* b2        = (const float*)d_in[21];
    const float* fin_g     = (const float*)d_in[22];
    const float* fin_b     = (const float*)d_in[23];
    float* out = (float*)d_out;

    float *px, *pout, *pqkv, *pbqkv;
    __nv_bfloat16 *phb, *pctxb, *phidb, *pwbf;
    cudaGetSymbolAddress((void**)&px,    g_x);
    cudaGetSymbolAddress((void**)&pout,  g_out);
    cudaGetSymbolAddress((void**)&pqkv,  g_qkv);
    cudaGetSymbolAddress((void**)&pbqkv, g_bqkv);
    cudaGetSymbolAddress((void**)&phb,   g_hb);
    cudaGetSymbolAddress((void**)&pctxb, g_ctxb);
    cudaGetSymbolAddress((void**)&phidb, g_hidb);
    cudaGetSymbolAddress((void**)&pwbf,  g_wbf);

    cudaFuncSetAttribute(attn_tc_kernel, cudaFuncAttributeMaxDynamicSharedMemorySize, ATTN_SMEM_BYTES);
    cudaFuncSetAttribute(gemm_tc<128>, cudaFuncAttributeMaxDynamicSharedMemorySize, GSMEM(128));
    cudaFuncSetAttribute(gemm_tc<64>,  cudaFuncAttributeMaxDynamicSharedMemorySize, GSMEM(64));

    prep_w<<<(PREP_TOT + NL*NQKV + 255) / 256, 256>>>(Wq, Wk, Wv, Wo, W1, W2, bq, bk, bv);
    embed_kernel<<<(MTOK * D + 255) / 256, 256>>>(src);

    const float qscale = 1.0f / sqrtf((float)DH);
    for (int l = 0; l < NL; l++) {
        ln_kernel<<<MTOK/8, 256>>>(px, phb, ln1_g + l * D, ln1_b + l * D);

        gemm_tc<128><<<dim3(NQKV/64, MTOK/128), 128, GSMEM(128)>>>(
            phb, pwbf + QKVW_OFF + (size_t)l * NQKV * D, pbqkv + l * NQKV, nullptr,
            pqkv, nullptr, MTOK, NQKV, D, qscale, 512, 0);

        attn_tc_kernel<<<dim3(B * H, 2), 256, ATTN_SMEM_BYTES>>>(
            distances, lengths, u, v, rel_table + (size_t)l * NBUCK * D);

        gemm_tc<64><<<dim3(D/64, MTOK/64), 128, GSMEM(64)>>>(
            pctxb, pwbf + WO_OFF + (size_t)l * D * D, bo + l * D, px,
            pout, nullptr, MTOK, D, D, 1.0f, D, 0);

        ln_kernel<<<MTOK/8, 256>>>(pout, phb, ffn_ln_g + l * D, ffn_ln_b + l * D);

        gemm_tc<128><<<dim3(DFF/64, MTOK/128), 128, GSMEM(128)>>>(
            phb, pwbf + W1_OFF + (size_t)l * DFF * D, b1 + l * DFF, nullptr,
            nullptr, phidb, MTOK, DFF, D, 1.0f, DFF, 1);

        gemm_tc<64><<<dim3(D/64, MTOK/64), 128, GSMEM(64)>>>(
            phidb, pwbf + W2_OFF + (size_t)l * DFF * D, b2 + l * D, pout,
            px, nullptr, MTOK, D, DFF, 1.0f, D, 0);
    }

    final_kernel<<<MTOK/8, 256>>>(fin_g, fin_b, out);
}

// round 16
// speedup vs baseline: 1.0552x; 1.0552x over previous
#include <cuda_runtime.h>
#include <cuda_bf16.h>
#include <math.h>

#define NL 4
#define D 512
#define H 8
#define DFF 2048
#define T 256
#define B 8
#define NBUCK 33
#define DH 64
#define MTOK (B*T)   // 2048
#define NQKV 1536

// bf16 weight buffer offsets (elements)
#define QKVW_OFF 0
#define WO_OFF   (NL*NQKV*D)
#define W1_OFF   (WO_OFF + NL*D*D)
#define W2_OFF   (W1_OFF + NL*DFF*D)
#define WTOT     (W2_OFF + NL*D*DFF)

// prep granule counts (float4 granules)
#define QKV4 (NL*NQKV*D/4)
#define WO4  (NL*D*D/4)
#define WFF4 (NL*DFF*D/4)
#define PREP_TOT (QKV4 + WO4 + 2*WFF4)

// ---------------- scratch ----------------
__device__ float g_x[MTOK*D];
__device__ float g_out[MTOK*D];
__device__ float g_bqkv[NL*NQKV];
__device__ __nv_bfloat16 g_qkvb[MTOK*NQKV];   // QKV bf16 end-to-end
__device__ __nv_bfloat16 g_hb[MTOK*D];
__device__ __nv_bfloat16 g_ctxb[MTOK*D];
__device__ __nv_bfloat16 g_hidb[MTOK*DFF];
__device__ __nv_bfloat16 g_wbf[WTOT];

// ---------------- merged weight prep (weights + qkv bias) -------------------
__global__ void prep_w(const float* __restrict__ Wq, const float* __restrict__ Wk,
                       const float* __restrict__ Wv, const float* __restrict__ Wo,
                       const float* __restrict__ W1, const float* __restrict__ W2,
                       const float* __restrict__ bq, const float* __restrict__ bk,
                       const float* __restrict__ bv) {
    int i = blockIdx.x * blockDim.x + threadIdx.x;
    if (i < QKV4) {
        int e = i * 4;
        int l = e / (NQKV*D);
        int rem = e - l * (NQKV*D);
        int r = rem / D;
        int c = rem - r * D;
        const float* s = (r < 512) ? Wq : (r < 1024) ? Wk : Wv;
        float4 v = *(const float4*)(s + (size_t)l*D*D + (size_t)(r & 511)*D + c);
        __nv_bfloat162* o = (__nv_bfloat162*)(g_wbf + QKVW_OFF + e);
        o[0] = __floats2bfloat162_rn(v.x, v.y);
        o[1] = __floats2bfloat162_rn(v.z, v.w);
    } else if (i < QKV4 + WO4) {
        int j = i - QKV4;
        float4 v = ((const float4*)Wo)[j];
        __nv_bfloat162* o = (__nv_bfloat162*)(g_wbf + WO_OFF + (size_t)j*4);
        o[0] = __floats2bfloat162_rn(v.x, v.y);
        o[1] = __floats2bfloat162_rn(v.z, v.w);
    } else if (i < QKV4 + WO4 + WFF4) {
        int j = i - QKV4 - WO4;
        float4 v = ((const float4*)W1)[j];
        __nv_bfloat162* o = (__nv_bfloat162*)(g_wbf + W1_OFF + (size_t)j*4);
        o[0] = __floats2bfloat162_rn(v.x, v.y);
        o[1] = __floats2bfloat162_rn(v.z, v.w);
    } else if (i < PREP_TOT) {
        int j = i - QKV4 - WO4 - WFF4;
        float4 v = ((const float4*)W2)[j];
        __nv_bfloat162* o = (__nv_bfloat162*)(g_wbf + W2_OFF + (size_t)j*4);
        o[0] = __floats2bfloat162_rn(v.x, v.y);
        o[1] = __floats2bfloat162_rn(v.z, v.w);
    } else if (i < PREP_TOT + NL*NQKV) {
        int j = i - PREP_TOT;
        int l = j / NQKV, n = j - l*NQKV;
        float v = (n < 512) ? bq[l*D + n] : (n < 1024) ? bk[l*D + n - 512] : bv[l*D + n - 1024];
        g_bqkv[j] = v;
    }
}

// ---------------- embedding ------------------------------------------------
__global__ void embed_kernel(const float* __restrict__ src) {
    int i = blockIdx.x * blockDim.x + threadIdx.x;
    if (i >= MTOK * D) return;
    int d = i & (D - 1);
    int t = (i / D) & (T - 1);
    int b = i / (D * T);
    float ang = (float)t * expf(-(float)(d & ~1) * (logf(10000.0f) / (float)D));
    float pe = (d & 1) ? cosf(ang) : sinf(ang);
    g_x[i] = src[((t * B) + b) * D + d] * sqrtf((float)D) + pe;
}

// ---------------- warp-per-token layernorm -> bf16 -------------------------
__global__ __launch_bounds__(256) void ln_kernel(const float* __restrict__ in,
                                                 __nv_bfloat16* __restrict__ out,
                                                 const float* __restrict__ gam,
                                                 const float* __restrict__ bet) {
    int lane = threadIdx.x & 31, w = threadIdx.x >> 5;
    int tok = blockIdx.x * 8 + w;
    const float4* row = (const float4*)(in + (size_t)tok * D);
    float4 v[4];
    float s = 0.f;
    #pragma unroll
    for (int j = 0; j < 4; j++) {
        v[j] = row[lane + 32*j];
        s += v[j].x + v[j].y + v[j].z + v[j].w;
    }
    #pragma unroll
    for (int o = 16; o; o >>= 1) s += __shfl_xor_sync(0xffffffffu, s, o);
    float mean = s * (1.0f / D);
    float sq = 0.f;
    #pragma unroll
    for (int j = 0; j < 4; j++) {
        v[j].x -= mean; v[j].y -= mean; v[j].z -= mean; v[j].w -= mean;
        sq += v[j].x*v[j].x + v[j].y*v[j].y + v[j].z*v[j].z + v[j].w*v[j].w;
    }
    #pragma unroll
    for (int o = 16; o; o >>= 1) sq += __shfl_xor_sync(0xffffffffu, sq, o);
    float inv = rsqrtf(sq * (1.0f / D) + 1e-6f);
    __nv_bfloat162* o2 = (__nv_bfloat162*)(out + (size_t)tok * D);
    #pragma unroll
    for (int j = 0; j < 4; j++) {
        int idx = lane + 32*j;
        float4 gv = ((const float4*)gam)[idx];
        float4 bv = ((const float4*)bet)[idx];
        o2[2*idx]   = __floats2bfloat162_rn(v[j].x * inv * gv.x + bv.x, v[j].y * inv * gv.y + bv.y);
        o2[2*idx+1] = __floats2bfloat162_rn(v[j].z * inv * gv.z + bv.z, v[j].w * inv * gv.w + bv.w);
    }
}

// ---------------- mma helpers ----------------------------------------------
__device__ __forceinline__ void mma_bf16(float* d, const unsigned* a, unsigned b0, unsigned b1) {
    asm volatile("mma.sync.aligned.m16n8k16.row.col.f32.bf16.bf16.f32 "
        "{%0,%1,%2,%3},{%4,%5,%6,%7},{%8,%9},{%0,%1,%2,%3};\n"
        : "+f"(d[0]), "+f"(d[1]), "+f"(d[2]), "+f"(d[3])
        : "r"(a[0]), "r"(a[1]), "r"(a[2]), "r"(a[3]), "r"(b0), "r"(b1));
}
__device__ __forceinline__ void ldsm4(unsigned* r, unsigned addr) {
    asm volatile("ldmatrix.sync.aligned.m8n8.x4.shared.b16 {%0,%1,%2,%3},[%4];\n"
        : "=r"(r[0]), "=r"(r[1]), "=r"(r[2]), "=r"(r[3]) : "r"(addr));
}
__device__ __forceinline__ void cp16(unsigned dst, const void* src) {
    asm volatile("cp.async.cg.shared.global [%0], [%1], 16;\n" :: "r"(dst), "l"(src));
}
__device__ __forceinline__ void cp_commit() { asm volatile("cp.async.commit_group;\n"); }
__device__ __forceinline__ void cp_wait0() { asm volatile("cp.async.wait_group 0;\n"); }
__device__ __forceinline__ unsigned packbf(float x, float y) {
    __nv_bfloat162 t = __floats2bfloat162_rn(x, y);
    return *(unsigned*)&t;
}

// ---------------- tensor-core GEMM, 2-stage cp.async (R12 config) ----------
#define GP 72
#define GSMEM(BM) (2 * ((BM) + 64) * GP * 2)

template<int BM>
__global__ __launch_bounds__(128, 4) void gemm_tc(
    const __nv_bfloat16* __restrict__ A, const __nv_bfloat16* __restrict__ W,
    const float* __restrict__ bias, const float* __restrict__ resid,
    float* __restrict__ Cf, __nv_bfloat16* __restrict__ Cb,
    int M, int N, int K, float scale, int n_lo, int relu)
{
    constexpr int MT = BM / 32;
    constexpr int AROWS = BM / 16;
    extern __shared__ __nv_bfloat16 smg[];
    __nv_bfloat16* As = smg;
    __nv_bfloat16* Bs = smg + 2*BM*GP;
    int tid = threadIdx.x;
    int lane = tid & 31, wid = tid >> 5;
    int wm = wid & 1, wn = wid >> 1;
    int m0 = blockIdx.y * BM, n0 = blockIdx.x << 6;

    int a_row = wm * (BM/2) + (lane & 15);
    int a_koff = (lane >> 4) << 3;
    int b_row = (wn << 5) + (lane & 7) + ((lane >> 4) << 3);
    int b_koff = ((lane >> 3) & 1) << 3;
    unsigned As_base = (unsigned)__cvta_generic_to_shared(As);
    unsigned Bs_base = (unsigned)__cvta_generic_to_shared(Bs);

    float acc[MT][4][4];
    #pragma unroll
    for (int i = 0; i < MT; i++)
        #pragma unroll
        for (int j = 0; j < 4; j++)
            #pragma unroll
            for (int r = 0; r < 4; r++) acc[i][j][r] = 0.f;

    const int KT = K >> 6;
    int c_row = tid >> 3, c_kc = (tid & 7) << 3;

    const __nv_bfloat16* Ag = A + (size_t)m0 * K;
    const __nv_bfloat16* Wg = W + (size_t)n0 * K;

    auto issue = [&](int kt, int s) {
        const __nv_bfloat16* a = Ag + (kt << 6);
        const __nv_bfloat16* w = Wg + (kt << 6);
        unsigned sa = As_base + (unsigned)((s * BM * GP) << 1);
        unsigned sb = Bs_base + (unsigned)((s * 64 * GP) << 1);
        #pragma unroll
        for (int i = 0; i < AROWS; i++) {
            int r = c_row + (i << 4);
            cp16(sa + (unsigned)((r * GP + c_kc) << 1), a + (size_t)r * K + c_kc);
        }
        #pragma unroll
        for (int i = 0; i < 4; i++) {
            int r = c_row + (i << 4);
            cp16(sb + (unsigned)((r * GP + c_kc) << 1), w + (size_t)r * K + c_kc);
        }
        cp_commit();
    };

    issue(0, 0);
    for (int kt = 0; kt < KT; kt++) {
        int s = kt & 1;
        cp_wait0();
        __syncthreads();
        if (kt + 1 < KT) issue(kt + 1, s ^ 1);
        unsigned sa = As_base + (unsigned)((s * BM * GP) << 1);
        unsigned sb = Bs_base + (unsigned)((s * 64 * GP) << 1);
        #pragma unroll
        for (int st = 0; st < 4; st++) {
            unsigned av[MT][4], bv[2][4];
            unsigned abase = sa + (unsigned)((a_row * GP + (st << 4) + a_koff) << 1);
            #pragma unroll
            for (int i = 0; i < MT; i++)
                ldsm4(av[i], abase + (unsigned)((i << 4) * GP * 2));
            unsigned bbase = sb + (unsigned)((b_row * GP + (st << 4) + b_koff) << 1);
            ldsm4(bv[0], bbase);
            ldsm4(bv[1], bbase + (16 * GP * 2));
            #pragma unroll
            for (int i = 0; i < MT; i++)
                #pragma unroll
                for (int j = 0; j < 2; j++) {
                    mma_bf16(acc[i][2*j],   av[i], bv[j][0], bv[j][1]);
                    mma_bf16(acc[i][2*j+1], av[i], bv[j][2], bv[j][3]);
                }
        }
        __syncthreads();
    }

    float sc = (n0 < n_lo) ? scale : 1.0f;
    int rbase = m0 + wm * (BM/2) + (lane >> 2);
    int cbase = n0 + (wn << 5) + ((lane & 3) << 1);
    #pragma unroll
    for (int i = 0; i < MT; i++) {
        #pragma unroll
        for (int j = 0; j < 4; j++) {
            int r0 = rbase + (i << 4);
            int cc = cbase + (j << 3);
            float2 bb = *(const float2*)&bias[cc];
            float o0 = (acc[i][j][0] + bb.x) * sc;
            float o1 = (acc[i][j][1] + bb.y) * sc;
            float o2 = (acc[i][j][2] + bb.x) * sc;
            float o3 = (acc[i][j][3] + bb.y) * sc;
            if (relu) {
                o0 = fmaxf(o0, 0.f); o1 = fmaxf(o1, 0.f);
                o2 = fmaxf(o2, 0.f); o3 = fmaxf(o3, 0.f);
            }
            if (resid) {
                float2 ra = *(const float2*)&resid[(size_t)r0 * N + cc];
                float2 rb = *(const float2*)&resid[(size_t)(r0 + 8) * N + cc];
                o0 += ra.x; o1 += ra.y; o2 += rb.x; o3 += rb.y;
            }
            if (Cf) {
                *(float2*)&Cf[(size_t)r0 * N + cc] = make_float2(o0, o1);
                *(float2*)&Cf[(size_t)(r0 + 8) * N + cc] = make_float2(o2, o3);
            }
            if (Cb) {
                *(__nv_bfloat162*)&Cb[(size_t)r0 * N + cc] = __floats2bfloat162_rn(o0, o1);
                *(__nv_bfloat162*)&Cb[(size_t)(r0 + 8) * N + cc] = __floats2bfloat162_rn(o2, o3);
            }
        }
    }
}

// ---------------- tensor-core flash attention (+ fused srel) ---------------
// smem layout (bf16 regions first, 16B-aligned): Ksm | Vtsm | Qsm | Vst | relsm | srelsm
#define KS 72
#define VS 264
#define QS 72
#define VSTS 72
#define ATTN_SMEM_BYTES ((256*KS + 64*VS + 128*QS + 256*VSTS)*2 + (33*65 + 128*36)*4)

__global__ __launch_bounds__(256) void attn_tc_kernel(const int* __restrict__ distances,
                                                      const int* __restrict__ lengths,
                                                      const float* __restrict__ uvec,
                                                      const float* __restrict__ vvec,
                                                      const float* __restrict__ rel_table) {
    extern __shared__ char smraw[];
    __nv_bfloat16* Ksm  = (__nv_bfloat16*)smraw;              // 256*72
    __nv_bfloat16* Vtsm = Ksm + 256*KS;                       // 64*264
    __nv_bfloat16* Qsm  = Vtsm + 64*VS;                       // 128*72
    __nv_bfloat16* Vst  = Qsm + 128*QS;                       // 256*72  (16B-aligned base)
    float* relsm  = (float*)(Vst + 256*VSTS);                 // 33*65
    float* srelsm = relsm + 33*65;                            // 128*36

    int bh = blockIdx.x;
    int b = bh >> 3, h = bh & 7;
    int q0 = blockIdx.y << 7;
    int tid = threadIdx.x, lane = tid & 31, wid = tid >> 5;
    int len = lengths[b];
    int bT = b * T;
    const __nv_bfloat16* base = g_qkvb + (size_t)bT * NQKV;

    // K: raw 16B copies (8 bf16 per uint4); row stride 144B (16B multiple)
    for (int i = tid; i < 256*8; i += 256) {
        int key = i >> 3, c = (i & 7) << 3;
        uint4 v = *(const uint4*)(base + (size_t)key*NQKV + 512 + h*64 + c);
        *(uint4*)&Ksm[key*KS + c] = v;
    }
    // V staged coalesced as rows [key][dh]
    for (int i = tid; i < 256*8; i += 256) {
        int key = i >> 3, c = (i & 7) << 3;
        uint4 v = *(const uint4*)(base + (size_t)key*NQKV + 1024 + h*64 + c);
        *(uint4*)&Vst[key*VSTS + c] = v;
    }
    // rel table (this head)
    for (int i = tid; i < 33*64; i += 256) {
        int bk = i >> 6, d2 = i & 63;
        relsm[bk*65 + d2] = rel_table[bk*D + h*64 + d2];
    }
    // Q + u (convert, add, repack)
    for (int i = tid; i < 128*32; i += 256) {
        int q = i >> 5, dp = (i & 31) << 1;
        __nv_bfloat162 qv = *(const __nv_bfloat162*)(base + (size_t)(q0+q)*NQKV + h*64 + dp);
        float2 uu = *(const float2*)(uvec + h*64 + dp);
        *(__nv_bfloat162*)&Qsm[q*QS + dp] =
            __floats2bfloat162_rn(__bfloat162float(qv.x)+uu.x, __bfloat162float(qv.y)+uu.y);
    }
    __syncthreads();

    // smem transpose Vst -> Vtsm[dh][key]
    for (int i = tid; i < 64*128; i += 256) {
        int dh = i >> 7, kp = (i & 127) << 1;
        __nv_bfloat162 t;
        t.x = Vst[kp*VSTS + dh];
        t.y = Vst[(kp+1)*VSTS + dh];
        *(__nv_bfloat162*)&Vtsm[dh*VS + kp] = t;
    }

    // srel: warp -> its 16 queries; lane = bucket
    int wq = wid << 4;
    for (int qi = 0; qi < 16; qi++) {
        int q = q0 + wq + qi;
        float qv0 = __bfloat162float(base[(size_t)q*NQKV + h*64 + lane])      + vvec[h*64 + lane];
        float qv1 = __bfloat162float(base[(size_t)q*NQKV + h*64 + 32 + lane]) + vvec[h*64 + 32 + lane];
        const float* rrow = relsm + lane*65;
        float acc = 0.f;
        #pragma unroll
        for (int d2 = 0; d2 < 32; d2++)
            acc += __shfl_sync(0xffffffffu, qv0, d2) * rrow[d2];
        #pragma unroll
        for (int d2 = 0; d2 < 32; d2++)
            acc += __shfl_sync(0xffffffffu, qv1, d2) * rrow[32 + d2];
        srelsm[(wq+qi)*36 + lane] = acc;
        if (lane == 0) srelsm[(wq+qi)*36 + 32] = 0.f;
    }
    __syncthreads();

    unsigned Ks_base = (unsigned)__cvta_generic_to_shared(Ksm);
    unsigned Vs_base = (unsigned)__cvta_generic_to_shared(Vtsm);
    unsigned Qs_base = (unsigned)__cvta_generic_to_shared(Qsm);

    int a_row_q = wq + (lane & 15);
    int a_koff = (lane >> 4) << 3;
    int b_nrow = (lane & 7) + ((lane >> 4) << 3);
    int b_koff = ((lane >> 3) & 1) << 3;
    int r_lo = lane >> 2;
    int c4 = (lane & 3) << 1;

    float m_i0 = -1e30f, m_i1 = -1e30f, l_i0 = 0.f, l_i1 = 0.f;
    float ctx[8][4];
    #pragma unroll
    for (int t = 0; t < 8; t++)
        #pragma unroll
        for (int r = 0; r < 4; r++) ctx[t][r] = 0.f;

    for (int kc = 0; kc < 2; kc++) {
        int kbase = kc << 7;
        float S[16][4];
        #pragma unroll
        for (int j = 0; j < 16; j++)
            #pragma unroll
            for (int r = 0; r < 4; r++) S[j][r] = 0.f;

        #pragma unroll
        for (int st = 0; st < 4; st++) {
            unsigned av[4];
            ldsm4(av, Qs_base + (unsigned)((a_row_q*QS + (st << 4) + a_koff) << 1));
            #pragma unroll
            for (int j2 = 0; j2 < 8; j2++) {
                unsigned bv[4];
                ldsm4(bv, Ks_base + (unsigned)(((kbase + (j2 << 4) + b_nrow)*KS + (st << 4) + b_koff) << 1));
                mma_bf16(S[2*j2],   av, bv[0], bv[1]);
                mma_bf16(S[2*j2+1], av, bv[2], bv[3]);
            }
        }

        int qrow = wq + r_lo;
        const int* drow0 = distances + (size_t)(bT + q0 + qrow) * T + kbase + c4;
        const int* drow1 = drow0 + 8 * T;
        const float* sr0 = srelsm + qrow * 36;
        const float* sr1 = sr0 + 8 * 36;
        float mn0 = m_i0, mn1 = m_i1;
        #pragma unroll
        for (int j = 0; j < 16; j++) {
            int k = kbase + (j << 3) + c4;
            float s0 = S[j][0] + sr0[drow0[j*8]];
            float s1 = S[j][1] + sr0[drow0[j*8 + 1]];
            float s2 = S[j][2] + sr1[drow1[j*8]];
            float s3 = S[j][3] + sr1[drow1[j*8 + 1]];
            bool v0 = k < len, v1 = (k + 1) < len;
            s0 = v0 ? s0 : -1e30f; s1 = v1 ? s1 : -1e30f;
            s2 = v0 ? s2 : -1e30f; s3 = v1 ? s3 : -1e30f;
            S[j][0] = s0; S[j][1] = s1; S[j][2] = s2; S[j][3] = s3;
            mn0 = fmaxf(mn0, fmaxf(s0, s1));
            mn1 = fmaxf(mn1, fmaxf(s2, s3));
        }
        mn0 = fmaxf(mn0, __shfl_xor_sync(0xffffffffu, mn0, 1));
        mn0 = fmaxf(mn0, __shfl_xor_sync(0xffffffffu, mn0, 2));
        mn1 = fmaxf(mn1, __shfl_xor_sync(0xffffffffu, mn1, 1));
        mn1 = fmaxf(mn1, __shfl_xor_sync(0xffffffffu, mn1, 2));

        float ps0 = __expf(m_i0 - mn0), ps1 = __expf(m_i1 - mn1);
        float ls0 = 0.f, ls1 = 0.f;
        #pragma unroll
        for (int j = 0; j < 16; j++) {
            S[j][0] = __expf(S[j][0] - mn0);
            S[j][1] = __expf(S[j][1] - mn0);
            S[j][2] = __expf(S[j][2] - mn1);
            S[j][3] = __expf(S[j][3] - mn1);
            ls0 += S[j][0] + S[j][1];
            ls1 += S[j][2] + S[j][3];
        }
        ls0 += __shfl_xor_sync(0xffffffffu, ls0, 1);
        ls0 += __shfl_xor_sync(0xffffffffu, ls0, 2);
        ls1 += __shfl_xor_sync(0xffffffffu, ls1, 1);
        ls1 += __shfl_xor_sync(0xffffffffu, ls1, 2);
        l_i0 = l_i0 * ps0 + ls0;
        l_i1 = l_i1 * ps1 + ls1;
        m_i0 = mn0; m_i1 = mn1;
        #pragma unroll
        for (int t = 0; t < 8; t++) {
            ctx[t][0] *= ps0; ctx[t][1] *= ps0;
            ctx[t][2] *= ps1; ctx[t][3] *= ps1;
        }

        #pragma unroll
        for (int t = 0; t < 8; t++) {
            unsigned aP[4];
            aP[0] = packbf(S[2*t][0],   S[2*t][1]);
            aP[1] = packbf(S[2*t][2],   S[2*t][3]);
            aP[2] = packbf(S[2*t+1][0], S[2*t+1][1]);
            aP[3] = packbf(S[2*t+1][2], S[2*t+1][3]);
            #pragma unroll
            for (int v4 = 0; v4 < 4; v4++) {
                unsigned bv[4];
                ldsm4(bv, Vs_base + (unsigned)((((v4 << 4) + b_nrow)*VS + kbase + (t << 4) + b_koff) << 1));
                mma_bf16(ctx[2*v4],   aP, bv[0], bv[1]);
                mma_bf16(ctx[2*v4+1], aP, bv[2], bv[3]);
            }
        }
    }

    float inv0 = 1.0f / l_i0, inv1 = 1.0f / l_i1;
    int qa = bT + q0 + wq + r_lo;
    #pragma unroll
    for (int t = 0; t < 8; t++) {
        int dh = ((t >> 1) << 4) + ((t & 1) << 3) + c4;
        *(__nv_bfloat162*)&g_ctxb[(size_t)qa * D + h*64 + dh] =
            __floats2bfloat162_rn(ctx[t][0] * inv0, ctx[t][1] * inv0);
        *(__nv_bfloat162*)&g_ctxb[(size_t)(qa + 8) * D + h*64 + dh] =
            __floats2bfloat162_rn(ctx[t][2] * inv1, ctx[t][3] * inv1);
    }
}

// ---------------- final LN + transpose (warp per token) --------------------
__global__ __launch_bounds__(256) void final_kernel(const float* __restrict__ gam,
                                                    const float* __restrict__ bet,
                                                    float* __restrict__ out) {
    int lane = threadIdx.x & 31, w = threadIdx.x >> 5;
    int tok = blockIdx.x * 8 + w;
    int b = tok / T, t = tok % T;
    const float4* row = (const float4*)(g_x + (size_t)tok * D);
    float4 v[4];
    float s = 0.f;
    #pragma unroll
    for (int j = 0; j < 4; j++) {
        v[j] = row[lane + 32*j];
        s += v[j].x + v[j].y + v[j].z + v[j].w;
    }
    #pragma unroll
    for (int o = 16; o; o >>= 1) s += __shfl_xor_sync(0xffffffffu, s, o);
    float mean = s * (1.0f / D);
    float sq = 0.f;
    #pragma unroll
    for (int j = 0; j < 4; j++) {
        v[j].x -= mean; v[j].y -= mean; v[j].z -= mean; v[j].w -= mean;
        sq += v[j].x*v[j].x + v[j].y*v[j].y + v[j].z*v[j].z + v[j].w*v[j].w;
    }
    #pragma unroll
    for (int o = 16; o; o >>= 1) sq += __shfl_xor_sync(0xffffffffu, sq, o);
    float inv = rsqrtf(sq * (1.0f / D) + 1e-6f);
    float4* orow = (float4*)(out + (size_t)((t * B) + b) * D);
    #pragma unroll
    for (int j = 0; j < 4; j++) {
        int idx = lane + 32*j;
        float4 gv = ((const float4*)gam)[idx];
        float4 bv = ((const float4*)bet)[idx];
        float4 o;
        o.x = v[j].x * inv * gv.x + bv.x;
        o.y = v[j].y * inv * gv.y + bv.y;
        o.z = v[j].z * inv * gv.z + bv.z;
        o.w = v[j].w * inv * gv.w + bv.w;
        orow[idx] = o;
    }
}

// ---------------- host ----------------
extern "C" void kernel_launch(void* const* d_in, const int* in_sizes, int n_in,
                              void* d_out, int out_size) {
    const float* src       = (const float*)d_in[0];
    const int*   lengths   = (const int*)  d_in[1];
    const int*   distances = (const int*)  d_in[2];
    const float* u         = (const float*)d_in[3];
    const float* v         = (const float*)d_in[4];
    const float* ln1_g     = (const float*)d_in[5];
    const float* ln1_b     = (const float*)d_in[6];
    const float* Wq        = (const float*)d_in[7];
    const float* Wk        = (const float*)d_in[8];
    const float* Wv        = (const float*)d_in[9];
    const float* Wo        = (const float*)d_in[10];
    const float* bq        = (const float*)d_in[11];
    const float* bk        = (const float*)d_in[12];
    const float* bv        = (const float*)d_in[13];
    const float* bo        = (const float*)d_in[14];
    const float* rel_table = (const float*)d_in[15];
    const float* ffn_ln_g  = (const float*)d_in[16];
    const float* ffn_ln_b  = (const float*)d_in[17];
    const float* W1        = (const float*)d_in[18];
    const float* b1        = (const float*)d_in[19];
    const float* W2        = (const float*)d_in[20];
    const float* b2        = (const float*)d_in[21];
    const float* fin_g     = (const float*)d_in[22];
    const float* fin_b     = (const float*)d_in[23];
    float* out = (float*)d_out;

    float *px, *pout, *pbqkv;
    __nv_bfloat16 *phb, *pctxb, *phidb, *pwbf, *pqkvb;
    cudaGetSymbolAddress((void**)&px,    g_x);
    cudaGetSymbolAddress((void**)&pout,  g_out);
    cudaGetSymbolAddress((void**)&pbqkv, g_bqkv);
    cudaGetSymbolAddress((void**)&phb,   g_hb);
    cudaGetSymbolAddress((void**)&pctxb, g_ctxb);
    cudaGetSymbolAddress((void**)&phidb, g_hidb);
    cudaGetSymbolAddress((void**)&pwbf,  g_wbf);
    cudaGetSymbolAddress((void**)&pqkvb, g_qkvb);

    cudaFuncSetAttribute(attn_tc_kernel, cudaFuncAttributeMaxDynamicSharedMemorySize, ATTN_SMEM_BYTES);
    cudaFuncSetAttribute(gemm_tc<128>, cudaFuncAttributeMaxDynamicSharedMemorySize, GSMEM(128));
    cudaFuncSetAttribute(gemm_tc<64>,  cudaFuncAttributeMaxDynamicSharedMemorySize, GSMEM(64));

    prep_w<<<(PREP_TOT + NL*NQKV + 255) / 256, 256>>>(Wq, Wk, Wv, Wo, W1, W2, bq, bk, bv);
    embed_kernel<<<(MTOK * D + 255) / 256, 256>>>(src);

    const float qscale = 1.0f / sqrtf((float)DH);
    for (int l = 0; l < NL; l++) {
        ln_kernel<<<MTOK/8, 256>>>(px, phb, ln1_g + l * D, ln1_b + l * D);

        gemm_tc<128><<<dim3(NQKV/64, MTOK/128), 128, GSMEM(128)>>>(
            phb, pwbf + QKVW_OFF + (size_t)l * NQKV * D, pbqkv + l * NQKV, nullptr,
            nullptr, pqkvb, MTOK, NQKV, D, qscale, 512, 0);

        attn_tc_kernel<<<dim3(B * H, 2), 256, ATTN_SMEM_BYTES>>>(
            distances, lengths, u, v, rel_table + (size_t)l * NBUCK * D);

        gemm_tc<64><<<dim3(D/64, MTOK/64), 128, GSMEM(64)>>>(
            pctxb, pwbf + WO_OFF + (size_t)l * D * D, bo + l * D, px,
            pout, nullptr, MTOK, D, D, 1.0f, D, 0);

        ln_kernel<<<MTOK/8, 256>>>(pout, phb, ffn_ln_g + l * D, ffn_ln_b + l * D);

        gemm_tc<128><<<dim3(DFF/64, MTOK/128), 128, GSMEM(128)>>>(
            phb, pwbf + W1_OFF + (size_t)l * DFF * D, b1 + l * DFF, nullptr,
            nullptr, phidb, MTOK, DFF, D, 1.0f, DFF, 1);

        gemm_tc<64><<<dim3(D/64, MTOK/64), 128, GSMEM(64)>>>(
            phidb, pwbf + W2_OFF + (size_t)l * DFF * D, b2 + l * D, pout,
            px, nullptr, MTOK, D, DFF, 1.0f, D, 0);
    }

    final_kernel<<<MTOK/8, 256>>>(fin_g, fin_b, out);
}